// round 8
// baseline (speedup 1.0000x reference)
#include <cuda_runtime.h>
#include <cuda_bf16.h>

// Problem constants (fixed by the dataset)
#define NN      100000
#define NE      1600000
#define F_IN    128
#define F_HID   64
#define F_OUT   64

// -------- scratch (device globals; no allocation allowed) --------
__device__ __align__(16) float d_g   [NN * 64];  // (h @ W) * dis[row]  (per layer)
__device__ __align__(16) float d_h   [NN * 64];  // layer-1 output (post relu)
__device__ __align__(16) float d_sums[NN * 64];  // scatter-mean sums
__device__ int   d_src[NE];
__device__ int   d_dst[NE];
__device__ int   d_csr_src[NE];                  // dst-sorted src ids
__device__ int   d_rowptr[NN + 1];
__device__ int   d_cursor[NN];
__device__ int   d_user[NN];
__device__ float d_dis[NN];
__device__ int   d_deg[NN];
__device__ int   d_cnt[NN];
__device__ int   d_odd_or;     // 0 after detect => indices are int64

// 16-byte vector atomic add to global (explicit cvta -> red.global is safe).
__device__ __forceinline__ void atomic_add_f4(float* addr, float4 v) {
    unsigned long long ga;
    asm("cvta.to.global.u64 %0, %1;" : "=l"(ga) : "l"(addr));
    asm volatile("red.global.add.v4.f32 [%0], {%1, %2, %3, %4};"
                 :: "l"(ga), "f"(v.x), "f"(v.y), "f"(v.z), "f"(v.w) : "memory");
}

// ---------------------------------------------------------------
// Zero all per-replay scratch (graph-replay safe; no memset nodes).
__global__ void zero_init() {
    int t = blockIdx.x * blockDim.x + threadIdx.x;
    if (t == 0) d_odd_or = 0;
    if (t < NN * 16)
        ((float4*)d_sums)[t] = make_float4(0.f, 0.f, 0.f, 0.f);
    if (t < NN / 4) {                                 // NN divisible by 4
        ((int4*)d_deg)[t] = make_int4(0, 0, 0, 0);
        ((int4*)d_cnt)[t] = make_int4(0, 0, 0, 0);
    }
}

// ---------------------------------------------------------------
// Detect index dtype: OR the odd 32-bit words of the first 2048 entries.
__global__ void detect_kernel(const int* __restrict__ ei_words) {
    int x = 0;
    for (int i = threadIdx.x; i < 2048; i += blockDim.x)
        x |= ei_words[2 * i + 1];
    x |= __shfl_xor_sync(0xffffffff, x, 16);
    x |= __shfl_xor_sync(0xffffffff, x, 8);
    x |= __shfl_xor_sync(0xffffffff, x, 4);
    x |= __shfl_xor_sync(0xffffffff, x, 2);
    x |= __shfl_xor_sync(0xffffffff, x, 1);
    if ((threadIdx.x & 31) == 0 && x) atomicOr(&d_odd_or, 1);
}

// ---------------------------------------------------------------
// Normalize edge indices to int32, fuse degree histogram.
__global__ void convert_edges(const void* __restrict__ ei) {
    int t = blockIdx.x * blockDim.x + threadIdx.x;
    if (t >= NE) return;
    int s, d;
    if (d_odd_or == 0) {  // int64
        s = (int)((const long long*)ei)[t];
        d = (int)((const long long*)ei)[NE + t];
    } else {              // int32
        s = ((const int*)ei)[t];
        d = ((const int*)ei)[NE + t];
    }
    d_src[t] = s;
    d_dst[t] = d;
    atomicAdd(&d_deg[d], 1);
}

__global__ void convert_user(const void* __restrict__ u) {
    int t = blockIdx.x * blockDim.x + threadIdx.x;
    if (t >= NN) return;
    d_user[t] = (d_odd_or == 0) ? (int)((const long long*)u)[t]
                                : ((const int*)u)[t];
}

// ---------------------------------------------------------------
// Exclusive scan of deg -> rowptr & cursor; also dis = rsqrt(deg+1).
// Single block, 1024 threads, each owns a contiguous chunk.
#define SCAN_T 1024
#define CHUNK  ((NN + SCAN_T - 1) / SCAN_T)   // 98
__global__ void scan_kernel() {
    __shared__ int sm_s[SCAN_T];
    int tid = threadIdx.x;
    int beg = tid * CHUNK;
    int end = min(beg + CHUNK, NN);
    int mysum = 0;
    for (int i = beg; i < end; i++) mysum += d_deg[i];
    sm_s[tid] = mysum;
    __syncthreads();
    // Hillis-Steele inclusive scan
    for (int off = 1; off < SCAN_T; off <<= 1) {
        int v = (tid >= off) ? sm_s[tid - off] : 0;
        __syncthreads();
        sm_s[tid] += v;
        __syncthreads();
    }
    int run = sm_s[tid] - mysum;  // exclusive prefix of this chunk
    for (int i = beg; i < end; i++) {
        int dg = d_deg[i];
        d_rowptr[i] = run;
        d_cursor[i] = run;
        d_dis[i]    = rsqrtf((float)(dg + 1));  // +1 self loop; always > 0
        run += dg;
    }
    if (tid == 0) d_rowptr[NN] = NE;
}

// ---------------------------------------------------------------
// Bucket scatter: csr_src[pos(dst)] = src
__global__ void bucket_scatter() {
    int t = blockIdx.x * blockDim.x + threadIdx.x;
    if (t >= NE) return;
    int pos = atomicAdd(&d_cursor[d_dst[t]], 1);
    d_csr_src[pos] = d_src[t];
}

// ---------------------------------------------------------------
// G[r, :] = dis[r] * (X[r, :] @ W)     W is [K, 64] row-major.
// blockDim (16, 8) = 128 threads. 64 rows/block. Each thread: 8 rows x 4 cols.
template <int K>
__global__ void gemm_scale(const float* __restrict__ X, const float* __restrict__ W) {
    extern __shared__ float sm[];
    float* Ws = sm;            // K * 64
    float* Xs = sm + K * 64;   // 64 * K
    const int tid  = threadIdx.y * 16 + threadIdx.x;
    const int row0 = blockIdx.x * 64;

    for (int i = tid; i < K * 16; i += 128)
        ((float4*)Ws)[i] = ((const float4*)W)[i];
    for (int i = tid; i < 16 * K; i += 128) {
        int r = i / (K / 4), c = i % (K / 4);
        int gr = row0 + r;
        ((float4*)Xs)[i] = (gr < NN) ? ((const float4*)X)[(size_t)gr * (K / 4) + c]
                                     : make_float4(0.f, 0.f, 0.f, 0.f);
    }
    __syncthreads();

    float acc[8][4];
#pragma unroll
    for (int j = 0; j < 8; j++) { acc[j][0] = acc[j][1] = acc[j][2] = acc[j][3] = 0.f; }

    const int c0 = threadIdx.x * 4;
#pragma unroll 4
    for (int k = 0; k < K; k++) {
        float4 w = *(const float4*)&Ws[k * 64 + c0];
#pragma unroll
        for (int j = 0; j < 8; j++) {
            float xv = Xs[(threadIdx.y + j * 8) * K + k];
            acc[j][0] += xv * w.x; acc[j][1] += xv * w.y;
            acc[j][2] += xv * w.z; acc[j][3] += xv * w.w;
        }
    }
#pragma unroll
    for (int j = 0; j < 8; j++) {
        int r = row0 + threadIdx.y + j * 8;
        if (r < NN) {
            float d = d_dis[r];
            *(float4*)&d_g[(size_t)r * 64 + c0] =
                make_float4(acc[j][0] * d, acc[j][1] * d, acc[j][2] * d, acc[j][3] * d);
        }
    }
}

// ---------------------------------------------------------------
// CSR gather + per-row reduce. 16 threads per row (float4 lanes).
// acc = sum_{s in N(r)} g[s]; returns fused epilogue value per variant.
__device__ __forceinline__ float4 row_gather(int r, int lane) {
    const float4* g4 = (const float4*)d_g;
    int beg = d_rowptr[r], end = d_rowptr[r + 1];
    float4 acc = make_float4(0.f, 0.f, 0.f, 0.f);
    int j = beg;
    for (; j + 1 < end; j += 2) {
        int s0 = __ldg(&d_csr_src[j]);
        int s1 = __ldg(&d_csr_src[j + 1]);
        float4 a = __ldg(&g4[(size_t)s0 * 16 + lane]);
        float4 b = __ldg(&g4[(size_t)s1 * 16 + lane]);
        acc.x += a.x + b.x; acc.y += a.y + b.y;
        acc.z += a.z + b.z; acc.w += a.w + b.w;
    }
    if (j < end) {
        int s0 = __ldg(&d_csr_src[j]);
        float4 a = __ldg(&g4[(size_t)s0 * 16 + lane]);
        acc.x += a.x; acc.y += a.y; acc.z += a.z; acc.w += a.w;
    }
    return acc;
}

// Layer 1: h[r] = relu(dis[r] * (acc + g[r]) + b1)
__global__ void gather_fin1(const float* __restrict__ b1) {
    int t = blockIdx.x * blockDim.x + threadIdx.x;
    int r = t >> 4;
    if (r >= NN) return;
    int lane = t & 15;
    float4 acc = row_gather(r, lane);
    float  d   = d_dis[r];
    float4 g   = *((const float4*)(d_g + (size_t)r * 64) + lane);
    float4 b   = ((const float4*)b1)[lane];
    float4 o;
    o.x = fmaxf(fmaf(d, acc.x + g.x, b.x), 0.f);
    o.y = fmaxf(fmaf(d, acc.y + g.y, b.y), 0.f);
    o.z = fmaxf(fmaf(d, acc.z + g.z, b.z), 0.f);
    o.w = fmaxf(fmaf(d, acc.w + g.w, b.w), 0.f);
    *((float4*)(d_h + (size_t)r * 64) + lane) = o;
}

// Layer 2: v = dis[r]*(acc + g[r]) + b2 ; sums[user[r]] += v ; cnt[user[r]]++
__global__ void gather_fin2(const float* __restrict__ b2) {
    int t = blockIdx.x * blockDim.x + threadIdx.x;
    int r = t >> 4;
    if (r >= NN) return;
    int lane = t & 15;
    float4 acc = row_gather(r, lane);
    float  d   = d_dis[r];
    float4 g   = *((const float4*)(d_g + (size_t)r * 64) + lane);
    float4 b   = ((const float4*)b2)[lane];
    float4 v;
    v.x = fmaf(d, acc.x + g.x, b.x);
    v.y = fmaf(d, acc.y + g.y, b.y);
    v.z = fmaf(d, acc.z + g.z, b.z);
    v.w = fmaf(d, acc.w + g.w, b.w);
    int u = d_user[r];
    atomic_add_f4(d_sums + (size_t)u * 64 + lane * 4, v);
    if (lane == 0) atomicAdd(&d_cnt[u], 1);
}

// ---------------------------------------------------------------
// out[u, :] = cnt[u] > 0 ? sums[u, :] / cnt[u] : 0
__global__ void out_mean(float* __restrict__ out) {
    int t = blockIdx.x * blockDim.x + threadIdx.x;
    if (t >= NN * 16) return;
    int r = t >> 4, lane = t & 15;
    int c = d_cnt[r];
    float4 s = *((const float4*)(d_sums + (size_t)r * 64) + lane);
    float4 o = make_float4(0.f, 0.f, 0.f, 0.f);
    if (c > 0) {
        float inv = 1.0f / (float)c;
        o = make_float4(s.x * inv, s.y * inv, s.z * inv, s.w * inv);
    }
    *((float4*)(out + (size_t)r * 64) + lane) = o;
}

// ---------------------------------------------------------------
extern "C" void kernel_launch(void* const* d_in, const int* in_sizes, int n_in,
                              void* d_out, int out_size) {
    const float* x    = (const float*)d_in[0];
    const void*  ei   = d_in[1];
    const void*  uidx = d_in[2];
    const float* W1   = (const float*)d_in[3];
    const float* b1   = (const float*)d_in[4];
    const float* W2   = (const float*)d_in[5];
    const float* b2   = (const float*)d_in[6];
    float*       out  = (float*)d_out;
    (void)in_sizes; (void)n_in; (void)out_size;

    cudaFuncSetAttribute(gemm_scale<128>, cudaFuncAttributeMaxDynamicSharedMemorySize,
                         (128 * 64 + 64 * 128) * (int)sizeof(float));

    void* p_h;
    cudaGetSymbolAddress(&p_h, d_h);   // host-side query, not a stream op

    const int TB = 256;

    // scratch zero, dtype detect, index normalize + degree histogram
    zero_init<<<(NN * 16 + TB - 1) / TB, TB>>>();
    detect_kernel<<<1, 256>>>((const int*)ei);
    convert_edges<<<(NE + TB - 1) / TB, TB>>>(ei);
    convert_user<<<(NN + TB - 1) / TB, TB>>>(uidx);

    // CSR build: scan (also computes dis) + bucket scatter
    scan_kernel<<<1, SCAN_T>>>();
    bucket_scatter<<<(NE + TB - 1) / TB, TB>>>();

    // ---- layer 1 ----
    gemm_scale<128><<<(NN + 63) / 64, dim3(16, 8),
                      (128 * 64 + 64 * 128) * sizeof(float)>>>(x, W1);
    gather_fin1<<<(NN * 16 + TB - 1) / TB, TB>>>(b1);

    // ---- layer 2 ----
    gemm_scale<64><<<(NN + 63) / 64, dim3(16, 8),
                     (64 * 64 + 64 * 64) * sizeof(float)>>>((const float*)p_h, W2);
    gather_fin2<<<(NN * 16 + TB - 1) / TB, TB>>>(b2);

    // ---- scatter-mean ----
    out_mean<<<(NN * 16 + TB - 1) / TB, TB>>>(out);
}

// round 9
// speedup vs baseline: 1.0094x; 1.0094x over previous
#include <cuda_runtime.h>
#include <cuda_bf16.h>

// Problem constants (fixed by the dataset)
#define NN      100000
#define NE      1600000
#define F_IN    128
#define F_HID   64
#define F_OUT   64

// -------- scratch (device globals; no allocation allowed) --------
__device__ __align__(16) float d_g   [NN * 64];  // (h @ W) * dis[row]  (per layer)
__device__ __align__(16) float d_h   [NN * 64];  // layer-1 output (post relu)
__device__ __align__(16) float d_sums[NN * 64];  // scatter-mean sums
__device__ int   d_src[NE];
__device__ int   d_dst[NE];
__device__ int   d_csr_src[NE];                  // dst-sorted src ids
__device__ int   d_rowptr[NN + 1];
__device__ int   d_cursor[NN];
__device__ int   d_user[NN];
__device__ float d_dis[NN];
__device__ int   d_deg[NN];
__device__ int   d_cnt[NN];
__device__ int   d_odd_or;     // 0 after detect => indices are int64

// 16-byte vector atomic add to global (explicit cvta -> red.global is safe).
__device__ __forceinline__ void atomic_add_f4(float* addr, float4 v) {
    unsigned long long ga;
    asm("cvta.to.global.u64 %0, %1;" : "=l"(ga) : "l"(addr));
    asm volatile("red.global.add.v4.f32 [%0], {%1, %2, %3, %4};"
                 :: "l"(ga), "f"(v.x), "f"(v.y), "f"(v.z), "f"(v.w) : "memory");
}

// ---------------------------------------------------------------
// Zero all per-replay scratch (graph-replay safe; no memset nodes).
__global__ void zero_init() {
    int t = blockIdx.x * blockDim.x + threadIdx.x;
    if (t == 0) d_odd_or = 0;
    if (t < NN * 16)
        ((float4*)d_sums)[t] = make_float4(0.f, 0.f, 0.f, 0.f);
    if (t < NN / 4) {                                 // NN divisible by 4
        ((int4*)d_deg)[t] = make_int4(0, 0, 0, 0);
        ((int4*)d_cnt)[t] = make_int4(0, 0, 0, 0);
    }
}

// ---------------------------------------------------------------
// Detect index dtype: OR the odd 32-bit words of the first 2048 entries.
// int64 (values < 2^31, nonneg) -> all high words zero -> d_odd_or stays 0.
__global__ void detect_kernel(const int* __restrict__ ei_words) {
    int x = 0;
    for (int i = threadIdx.x; i < 2048; i += blockDim.x)
        x |= ei_words[2 * i + 1];
    x |= __shfl_xor_sync(0xffffffff, x, 16);
    x |= __shfl_xor_sync(0xffffffff, x, 8);
    x |= __shfl_xor_sync(0xffffffff, x, 4);
    x |= __shfl_xor_sync(0xffffffff, x, 2);
    x |= __shfl_xor_sync(0xffffffff, x, 1);
    if ((threadIdx.x & 31) == 0 && x) atomicOr(&d_odd_or, 1);
}

// ---------------------------------------------------------------
// Normalize edge + user indices to int32, fuse degree histogram.
__global__ void convert_all(const void* __restrict__ ei, const void* __restrict__ u) {
    int t = blockIdx.x * blockDim.x + threadIdx.x;
    if (t >= NE) return;
    const bool i64 = (d_odd_or == 0);
    int s, d;
    if (i64) {
        s = (int)((const long long*)ei)[t];
        d = (int)((const long long*)ei)[NE + t];
    } else {
        s = ((const int*)ei)[t];
        d = ((const int*)ei)[NE + t];
    }
    d_src[t] = s;
    d_dst[t] = d;
    atomicAdd(&d_deg[d], 1);
    if (t < NN)
        d_user[t] = i64 ? (int)((const long long*)u)[t] : ((const int*)u)[t];
}

// ---------------------------------------------------------------
// Exclusive scan of deg -> rowptr & cursor; also dis = rsqrt(deg+1).
// Single block, 1024 threads, each owns a contiguous chunk.
#define SCAN_T 1024
#define CHUNK  ((NN + SCAN_T - 1) / SCAN_T)   // 98
__global__ void scan_kernel() {
    __shared__ int sm_s[SCAN_T];
    int tid = threadIdx.x;
    int beg = tid * CHUNK;
    int end = min(beg + CHUNK, NN);
    int mysum = 0;
    for (int i = beg; i < end; i++) mysum += d_deg[i];
    sm_s[tid] = mysum;
    __syncthreads();
    for (int off = 1; off < SCAN_T; off <<= 1) {
        int v = (tid >= off) ? sm_s[tid - off] : 0;
        __syncthreads();
        sm_s[tid] += v;
        __syncthreads();
    }
    int run = sm_s[tid] - mysum;  // exclusive prefix of this chunk
    for (int i = beg; i < end; i++) {
        int dg = d_deg[i];
        d_rowptr[i] = run;
        d_cursor[i] = run;
        d_dis[i]    = rsqrtf((float)(dg + 1));  // +1 self loop; always > 0
        run += dg;
    }
    if (tid == 0) d_rowptr[NN] = NE;
}

// ---------------------------------------------------------------
// Bucket scatter: csr_src[pos(dst)] = src
__global__ void bucket_scatter() {
    int t = blockIdx.x * blockDim.x + threadIdx.x;
    if (t >= NE) return;
    int pos = atomicAdd(&d_cursor[d_dst[t]], 1);
    d_csr_src[pos] = d_src[t];
}

// ---------------------------------------------------------------
// G[r, :] = dis[r] * (X[r, :] @ W)     W is [K, 64] row-major.
// blockDim (16, 8) = 128 threads. 64 rows/block. Each thread: 8 rows x 4 cols.
template <int K>
__global__ void gemm_scale(const float* __restrict__ X, const float* __restrict__ W) {
    extern __shared__ float sm[];
    float* Ws = sm;            // K * 64
    float* Xs = sm + K * 64;   // 64 * K
    const int tid  = threadIdx.y * 16 + threadIdx.x;
    const int row0 = blockIdx.x * 64;

    for (int i = tid; i < K * 16; i += 128)
        ((float4*)Ws)[i] = ((const float4*)W)[i];
    for (int i = tid; i < 16 * K; i += 128) {
        int r = i / (K / 4), c = i % (K / 4);
        int gr = row0 + r;
        ((float4*)Xs)[i] = (gr < NN) ? ((const float4*)X)[(size_t)gr * (K / 4) + c]
                                     : make_float4(0.f, 0.f, 0.f, 0.f);
    }
    __syncthreads();

    float acc[8][4];
#pragma unroll
    for (int j = 0; j < 8; j++) { acc[j][0] = acc[j][1] = acc[j][2] = acc[j][3] = 0.f; }

    const int c0 = threadIdx.x * 4;
#pragma unroll 4
    for (int k = 0; k < K; k++) {
        float4 w = *(const float4*)&Ws[k * 64 + c0];
#pragma unroll
        for (int j = 0; j < 8; j++) {
            float xv = Xs[(threadIdx.y + j * 8) * K + k];
            acc[j][0] += xv * w.x; acc[j][1] += xv * w.y;
            acc[j][2] += xv * w.z; acc[j][3] += xv * w.w;
        }
    }
#pragma unroll
    for (int j = 0; j < 8; j++) {
        int r = row0 + threadIdx.y + j * 8;
        if (r < NN) {
            float d = d_dis[r];
            *(float4*)&d_g[(size_t)r * 64 + c0] =
                make_float4(acc[j][0] * d, acc[j][1] * d, acc[j][2] * d, acc[j][3] * d);
        }
    }
}

// ---------------------------------------------------------------
// CSR gather + per-row reduce. 16 threads per row (float4 lanes).
// Unroll 4 with independent accumulator chains -> MLP >= 4 per group,
// flipping the kernel from L2-latency-bound to L2-throughput-bound.
__device__ __forceinline__ float4 row_gather(int r, int lane) {
    const float4* g4 = (const float4*)d_g;
    int beg = __ldg(&d_rowptr[r]), end = __ldg(&d_rowptr[r + 1]);
    float4 a0 = make_float4(0.f, 0.f, 0.f, 0.f);
    float4 a1 = a0, a2 = a0, a3 = a0;
    int j = beg;
#pragma unroll 1
    for (; j + 3 < end; j += 4) {
        int s0 = __ldg(&d_csr_src[j]);
        int s1 = __ldg(&d_csr_src[j + 1]);
        int s2 = __ldg(&d_csr_src[j + 2]);
        int s3 = __ldg(&d_csr_src[j + 3]);
        float4 v0 = __ldg(&g4[(size_t)s0 * 16 + lane]);
        float4 v1 = __ldg(&g4[(size_t)s1 * 16 + lane]);
        float4 v2 = __ldg(&g4[(size_t)s2 * 16 + lane]);
        float4 v3 = __ldg(&g4[(size_t)s3 * 16 + lane]);
        a0.x += v0.x; a0.y += v0.y; a0.z += v0.z; a0.w += v0.w;
        a1.x += v1.x; a1.y += v1.y; a1.z += v1.z; a1.w += v1.w;
        a2.x += v2.x; a2.y += v2.y; a2.z += v2.z; a2.w += v2.w;
        a3.x += v3.x; a3.y += v3.y; a3.z += v3.z; a3.w += v3.w;
    }
#pragma unroll 1
    for (; j < end; j++) {
        int s0 = __ldg(&d_csr_src[j]);
        float4 v0 = __ldg(&g4[(size_t)s0 * 16 + lane]);
        a0.x += v0.x; a0.y += v0.y; a0.z += v0.z; a0.w += v0.w;
    }
    a0.x += a1.x + a2.x + a3.x;
    a0.y += a1.y + a2.y + a3.y;
    a0.z += a1.z + a2.z + a3.z;
    a0.w += a1.w + a2.w + a3.w;
    return a0;
}

// Layer 1: h[r] = relu(dis[r] * (acc + g[r]) + b1)
__global__ void gather_fin1(const float* __restrict__ b1) {
    int t = blockIdx.x * blockDim.x + threadIdx.x;
    int r = t >> 4;
    if (r >= NN) return;
    int lane = t & 15;
    float4 acc = row_gather(r, lane);
    float  d   = d_dis[r];
    float4 g   = *((const float4*)(d_g + (size_t)r * 64) + lane);
    float4 b   = ((const float4*)b1)[lane];
    float4 o;
    o.x = fmaxf(fmaf(d, acc.x + g.x, b.x), 0.f);
    o.y = fmaxf(fmaf(d, acc.y + g.y, b.y), 0.f);
    o.z = fmaxf(fmaf(d, acc.z + g.z, b.z), 0.f);
    o.w = fmaxf(fmaf(d, acc.w + g.w, b.w), 0.f);
    *((float4*)(d_h + (size_t)r * 64) + lane) = o;
}

// Layer 2: v = dis[r]*(acc + g[r]) + b2 ; sums[user[r]] += v ; cnt[user[r]]++
__global__ void gather_fin2(const float* __restrict__ b2) {
    int t = blockIdx.x * blockDim.x + threadIdx.x;
    int r = t >> 4;
    if (r >= NN) return;
    int lane = t & 15;
    float4 acc = row_gather(r, lane);
    float  d   = d_dis[r];
    float4 g   = *((const float4*)(d_g + (size_t)r * 64) + lane);
    float4 b   = ((const float4*)b2)[lane];
    float4 v;
    v.x = fmaf(d, acc.x + g.x, b.x);
    v.y = fmaf(d, acc.y + g.y, b.y);
    v.z = fmaf(d, acc.z + g.z, b.z);
    v.w = fmaf(d, acc.w + g.w, b.w);
    int u = d_user[r];
    atomic_add_f4(d_sums + (size_t)u * 64 + lane * 4, v);
    if (lane == 0) atomicAdd(&d_cnt[u], 1);
}

// ---------------------------------------------------------------
// out[u, :] = cnt[u] > 0 ? sums[u, :] / cnt[u] : 0
__global__ void out_mean(float* __restrict__ out) {
    int t = blockIdx.x * blockDim.x + threadIdx.x;
    if (t >= NN * 16) return;
    int r = t >> 4, lane = t & 15;
    int c = d_cnt[r];
    float4 s = *((const float4*)(d_sums + (size_t)r * 64) + lane);
    float4 o = make_float4(0.f, 0.f, 0.f, 0.f);
    if (c > 0) {
        float inv = 1.0f / (float)c;
        o = make_float4(s.x * inv, s.y * inv, s.z * inv, s.w * inv);
    }
    *((float4*)(out + (size_t)r * 64) + lane) = o;
}

// ---------------------------------------------------------------
extern "C" void kernel_launch(void* const* d_in, const int* in_sizes, int n_in,
                              void* d_out, int out_size) {
    const float* x    = (const float*)d_in[0];
    const void*  ei   = d_in[1];
    const void*  uidx = d_in[2];
    const float* W1   = (const float*)d_in[3];
    const float* b1   = (const float*)d_in[4];
    const float* W2   = (const float*)d_in[5];
    const float* b2   = (const float*)d_in[6];
    float*       out  = (float*)d_out;
    (void)in_sizes; (void)n_in; (void)out_size;

    cudaFuncSetAttribute(gemm_scale<128>, cudaFuncAttributeMaxDynamicSharedMemorySize,
                         (128 * 64 + 64 * 128) * (int)sizeof(float));

    void* p_h;
    cudaGetSymbolAddress(&p_h, d_h);   // host-side query, not a stream op

    const int TB = 256;

    // scratch zero, dtype detect, index normalize + degree histogram
    zero_init<<<(NN * 16 + TB - 1) / TB, TB>>>();
    detect_kernel<<<1, 256>>>((const int*)ei);
    convert_all<<<(NE + TB - 1) / TB, TB>>>(ei, uidx);

    // CSR build: scan (also computes dis) + bucket scatter
    scan_kernel<<<1, SCAN_T>>>();
    bucket_scatter<<<(NE + TB - 1) / TB, TB>>>();

    // ---- layer 1 ----
    gemm_scale<128><<<(NN + 63) / 64, dim3(16, 8),
                      (128 * 64 + 64 * 128) * sizeof(float)>>>(x, W1);
    gather_fin1<<<(NN * 16 + TB - 1) / TB, TB>>>(b1);

    // ---- layer 2 ----
    gemm_scale<64><<<(NN + 63) / 64, dim3(16, 8),
                     (64 * 64 + 64 * 64) * sizeof(float)>>>((const float*)p_h, W2);
    gather_fin2<<<(NN * 16 + TB - 1) / TB, TB>>>(b2);

    // ---- scatter-mean ----
    out_mean<<<(NN * 16 + TB - 1) / TB, TB>>>(out);
}